// round 1
// baseline (speedup 1.0000x reference)
#include <cuda_runtime.h>
#include <cstdint>

// ---------------------------------------------------------------------------
// MTLoRALinear fused kernel (sm_103a), tf32 mma.sync path.
//   out[0]   = x@W^T + b + (x@A_sh^T)@B_sh^T
//   out[1+t] = x@W^T + b + scale_t * (x@A_t^T)@B_t^T
// Strategy:
//   K1: Y[M,80] = x @ concat(A_sh, A_tasks)^T   (tf32 GEMM, N padded to 128)
//   K2: P = x@W^T tile-wise; epilogue adds bias and per-head rank-16
//       correction via 2 extra mma k-steps, writes all 5 heads.
// ---------------------------------------------------------------------------

namespace {
constexpr int MTOT = 32768;       // B*S
constexpr int DK   = 1024;        // in features
constexpr int OK   = 1024;        // out features
constexpr int BM = 128, BN = 128, BK = 32;
constexpr int XST = 36;           // mainloop smem row stride (floats): 36/4=9 odd -> conflict free
constexpr int EST = 20;           // epilogue smem row stride (floats): 20/4=5 odd -> conflict free
}

// scratch for Y = x @ A_all^T  (32768 x 80 fp32 = 10.5 MB)
__device__ float g_Y[MTOT * 80];

__device__ __forceinline__ uint32_t tf32_rna(float x) {
    uint32_t u;
    asm("cvt.rna.tf32.f32 %0, %1;" : "=r"(u) : "f"(x));
    return u;
}

__device__ __forceinline__ void mma_tf32(float* c, const uint32_t* a, const uint32_t* b) {
    asm volatile(
        "mma.sync.aligned.m16n8k8.row.col.f32.tf32.tf32.f32 "
        "{%0,%1,%2,%3}, {%4,%5,%6,%7}, {%8,%9}, {%0,%1,%2,%3};\n"
        : "+f"(c[0]), "+f"(c[1]), "+f"(c[2]), "+f"(c[3])
        : "r"(a[0]), "r"(a[1]), "r"(a[2]), "r"(a[3]), "r"(b[0]), "r"(b[1]));
}

__device__ __forceinline__ void mma_tf32_dc(float* d, const float* c,
                                            const uint32_t* a, const uint32_t* b) {
    asm volatile(
        "mma.sync.aligned.m16n8k8.row.col.f32.tf32.tf32.f32 "
        "{%0,%1,%2,%3}, {%4,%5,%6,%7}, {%8,%9}, {%10,%11,%12,%13};\n"
        : "=f"(d[0]), "=f"(d[1]), "=f"(d[2]), "=f"(d[3])
        : "r"(a[0]), "r"(a[1]), "r"(a[2]), "r"(a[3]), "r"(b[0]), "r"(b[1]),
          "f"(c[0]), "f"(c[1]), "f"(c[2]), "f"(c[3]));
}

// ---------------------------------------------------------------------------
// Kernel 1: Y = x @ A_all^T, A_all rows 0..15 = A_sh, 16..79 = A_tasks, 80..127 = 0
// ---------------------------------------------------------------------------
__global__ __launch_bounds__(256) void lora_y_kernel(
    const float* __restrict__ x,
    const float* __restrict__ A_sh,
    const float* __restrict__ A_tasks)
{
    __shared__ float Xs[BM * XST];
    __shared__ float Ws[BN * XST];

    const int tid  = threadIdx.x;
    const int lane = tid & 31, wid = tid >> 5;
    const int wm = wid >> 2, wn = wid & 3;
    const int m0 = blockIdx.x * BM;

    const int lr = tid >> 3;          // 0..31, row base within tile
    const int lc = (tid & 7) << 2;    // k offset (float4 granularity)

    const float* xg = x + (size_t)(m0 + lr) * DK + lc;

    const float* ag[4];
    bool av[4];
#pragma unroll
    for (int i = 0; i < 4; i++) {
        const int r = lr + 32 * i;
        if (r < 16)      { ag[i] = A_sh    + (size_t)r * DK + lc;        av[i] = true; }
        else if (r < 80) { ag[i] = A_tasks + (size_t)(r - 16) * DK + lc; av[i] = true; }
        else             { ag[i] = A_sh + lc;                            av[i] = false; }
    }

    float4 px[4], pw[4];
    const float4 z4 = make_float4(0.f, 0.f, 0.f, 0.f);
#pragma unroll
    for (int i = 0; i < 4; i++) {
        px[i] = *reinterpret_cast<const float4*>(xg + (size_t)(32 * i) * DK);
        pw[i] = av[i] ? *reinterpret_cast<const float4*>(ag[i]) : z4;
    }

    float c[4][4][4];
#pragma unroll
    for (int i = 0; i < 4; i++)
#pragma unroll
        for (int j = 0; j < 4; j++)
#pragma unroll
            for (int q = 0; q < 4; q++) c[i][j][q] = 0.f;

    for (int kc = 0; kc < DK; kc += BK) {
        __syncthreads();
#pragma unroll
        for (int i = 0; i < 4; i++) {
            float* xs = &Xs[(lr + 32 * i) * XST + lc];
            xs[0] = __uint_as_float(tf32_rna(px[i].x));
            xs[1] = __uint_as_float(tf32_rna(px[i].y));
            xs[2] = __uint_as_float(tf32_rna(px[i].z));
            xs[3] = __uint_as_float(tf32_rna(px[i].w));
            float* ws = &Ws[(lr + 32 * i) * XST + lc];
            ws[0] = __uint_as_float(tf32_rna(pw[i].x));
            ws[1] = __uint_as_float(tf32_rna(pw[i].y));
            ws[2] = __uint_as_float(tf32_rna(pw[i].z));
            ws[3] = __uint_as_float(tf32_rna(pw[i].w));
        }
        __syncthreads();
        if (kc + BK < DK) {
#pragma unroll
            for (int i = 0; i < 4; i++) {
                px[i] = *reinterpret_cast<const float4*>(xg + (size_t)(32 * i) * DK + kc + BK);
                pw[i] = av[i] ? *reinterpret_cast<const float4*>(ag[i] + kc + BK) : z4;
            }
        }
#pragma unroll
        for (int ks = 0; ks < 4; ks++) {
            const int ak = ks * 8 + (lane & 3);
            const int ar = wm * 64 + (lane >> 2);
            uint32_t a[4][4];
#pragma unroll
            for (int i = 0; i < 4; i++) {
                const float* base = &Xs[(ar + i * 16) * XST + ak];
                a[i][0] = __float_as_uint(base[0]);
                a[i][1] = __float_as_uint(base[8 * XST]);
                a[i][2] = __float_as_uint(base[4]);
                a[i][3] = __float_as_uint(base[8 * XST + 4]);
            }
            uint32_t b[4][2];
            const int bn = wn * 32 + (lane >> 2);
#pragma unroll
            for (int j = 0; j < 4; j++) {
                const float* base = &Ws[(bn + j * 8) * XST + ak];
                b[j][0] = __float_as_uint(base[0]);
                b[j][1] = __float_as_uint(base[4]);
            }
#pragma unroll
            for (int i = 0; i < 4; i++)
#pragma unroll
                for (int j = 0; j < 4; j++)
                    mma_tf32(c[i][j], a[i], b[j]);
        }
    }

    // write Y (cols < 80 only)
#pragma unroll
    for (int j = 0; j < 4; j++) {
        const int colb = wn * 32 + j * 8 + (lane & 3) * 2;
        if (colb < 80) {
#pragma unroll
            for (int i = 0; i < 4; i++) {
                const int r0 = m0 + wm * 64 + i * 16 + (lane >> 2);
                *reinterpret_cast<float2*>(g_Y + (size_t)r0 * 80 + colb) =
                    make_float2(c[i][j][0], c[i][j][1]);
                *reinterpret_cast<float2*>(g_Y + (size_t)(r0 + 8) * 80 + colb) =
                    make_float2(c[i][j][2], c[i][j][3]);
            }
        }
    }
}

// ---------------------------------------------------------------------------
// Kernel 2: fused main GEMM + bias + 5-head rank-16 corrections
// ---------------------------------------------------------------------------
__global__ __launch_bounds__(256) void fused_main(
    const float* __restrict__ x,
    const float* __restrict__ W,
    const float* __restrict__ bias,
    const float* __restrict__ B_sh,
    const float* __restrict__ B_tasks,
    const float* __restrict__ task_scales,
    float* __restrict__ out)
{
    __shared__ float Xs[BM * XST];
    __shared__ float Ws[BN * XST];

    const int tid  = threadIdx.x;
    const int lane = tid & 31, wid = tid >> 5;
    const int wm = wid >> 2, wn = wid & 3;
    const int m0 = blockIdx.y * BM, n0 = blockIdx.x * BN;

    const int lr = tid >> 3;
    const int lc = (tid & 7) << 2;

    const float* xg = x + (size_t)(m0 + lr) * DK + lc;
    const float* wg = W + (size_t)(n0 + lr) * DK + lc;

    float4 px[4], pw[4];
#pragma unroll
    for (int i = 0; i < 4; i++) {
        px[i] = *reinterpret_cast<const float4*>(xg + (size_t)(32 * i) * DK);
        pw[i] = *reinterpret_cast<const float4*>(wg + (size_t)(32 * i) * DK);
    }

    float c[4][4][4];
#pragma unroll
    for (int i = 0; i < 4; i++)
#pragma unroll
        for (int j = 0; j < 4; j++)
#pragma unroll
            for (int q = 0; q < 4; q++) c[i][j][q] = 0.f;

    for (int kc = 0; kc < DK; kc += BK) {
        __syncthreads();
#pragma unroll
        for (int i = 0; i < 4; i++) {
            float* xs = &Xs[(lr + 32 * i) * XST + lc];
            xs[0] = __uint_as_float(tf32_rna(px[i].x));
            xs[1] = __uint_as_float(tf32_rna(px[i].y));
            xs[2] = __uint_as_float(tf32_rna(px[i].z));
            xs[3] = __uint_as_float(tf32_rna(px[i].w));
            float* ws = &Ws[(lr + 32 * i) * XST + lc];
            ws[0] = __uint_as_float(tf32_rna(pw[i].x));
            ws[1] = __uint_as_float(tf32_rna(pw[i].y));
            ws[2] = __uint_as_float(tf32_rna(pw[i].z));
            ws[3] = __uint_as_float(tf32_rna(pw[i].w));
        }
        __syncthreads();
        if (kc + BK < DK) {
#pragma unroll
            for (int i = 0; i < 4; i++) {
                px[i] = *reinterpret_cast<const float4*>(xg + (size_t)(32 * i) * DK + kc + BK);
                pw[i] = *reinterpret_cast<const float4*>(wg + (size_t)(32 * i) * DK + kc + BK);
            }
        }
#pragma unroll
        for (int ks = 0; ks < 4; ks++) {
            const int ak = ks * 8 + (lane & 3);
            const int ar = wm * 64 + (lane >> 2);
            uint32_t a[4][4];
#pragma unroll
            for (int i = 0; i < 4; i++) {
                const float* base = &Xs[(ar + i * 16) * XST + ak];
                a[i][0] = __float_as_uint(base[0]);
                a[i][1] = __float_as_uint(base[8 * XST]);
                a[i][2] = __float_as_uint(base[4]);
                a[i][3] = __float_as_uint(base[8 * XST + 4]);
            }
            uint32_t b[4][2];
            const int bn = wn * 32 + (lane >> 2);
#pragma unroll
            for (int j = 0; j < 4; j++) {
                const float* base = &Ws[(bn + j * 8) * XST + ak];
                b[j][0] = __float_as_uint(base[0]);
                b[j][1] = __float_as_uint(base[4]);
            }
#pragma unroll
            for (int i = 0; i < 4; i++)
#pragma unroll
                for (int j = 0; j < 4; j++)
                    mma_tf32(c[i][j], a[i], b[j]);
        }
    }

    // bias add (shared by all heads)
#pragma unroll
    for (int j = 0; j < 4; j++) {
        const int col = n0 + wn * 32 + j * 8 + (lane & 3) * 2;
        const float b0 = __ldg(bias + col);
        const float b1 = __ldg(bias + col + 1);
#pragma unroll
        for (int i = 0; i < 4; i++) {
            c[i][j][0] += b0; c[i][j][1] += b1;
            c[i][j][2] += b0; c[i][j][3] += b1;
        }
    }

    // per-head epilogue: corr = Y_h @ B_h^T + C, written straight out
    const int srow = tid >> 1;          // 0..127
    const int scb  = (tid & 1) * 8;     // 0 or 8

    for (int h = 0; h < 5; h++) {
        __syncthreads();   // previous head (or mainloop) done with smem

        // stage Y_h tile [128 x 16] into Xs (stride EST)
        {
            const float* ys = g_Y + (size_t)(m0 + srow) * 80 + h * 16 + scb;
            const float4 y0 = *reinterpret_cast<const float4*>(ys);
            const float4 y1 = *reinterpret_cast<const float4*>(ys + 4);
            float* yd = &Xs[srow * EST + scb];
            yd[0] = __uint_as_float(tf32_rna(y0.x));
            yd[1] = __uint_as_float(tf32_rna(y0.y));
            yd[2] = __uint_as_float(tf32_rna(y0.z));
            yd[3] = __uint_as_float(tf32_rna(y0.w));
            yd[4] = __uint_as_float(tf32_rna(y1.x));
            yd[5] = __uint_as_float(tf32_rna(y1.y));
            yd[6] = __uint_as_float(tf32_rna(y1.z));
            yd[7] = __uint_as_float(tf32_rna(y1.w));
        }
        // stage B_h tile [128 x 16] into Ws (scaled)
        {
            const float* bsrc;
            float sc = 1.0f;
            if (h == 0) {
                bsrc = B_sh + (size_t)(n0 + srow) * 16 + scb;
            } else {
                bsrc = B_tasks + ((size_t)(h - 1) * OK + n0 + srow) * 16 + scb;
                sc = __ldg(task_scales + (h - 1));
            }
            const float4 b0 = *reinterpret_cast<const float4*>(bsrc);
            const float4 b1 = *reinterpret_cast<const float4*>(bsrc + 4);
            float* bd = &Ws[srow * EST + scb];
            bd[0] = __uint_as_float(tf32_rna(b0.x * sc));
            bd[1] = __uint_as_float(tf32_rna(b0.y * sc));
            bd[2] = __uint_as_float(tf32_rna(b0.z * sc));
            bd[3] = __uint_as_float(tf32_rna(b0.w * sc));
            bd[4] = __uint_as_float(tf32_rna(b1.x * sc));
            bd[5] = __uint_as_float(tf32_rna(b1.y * sc));
            bd[6] = __uint_as_float(tf32_rna(b1.z * sc));
            bd[7] = __uint_as_float(tf32_rna(b1.w * sc));
        }
        __syncthreads();

        // A fragments from Y_h
        uint32_t ya[4][2][4];
        const int ar = wm * 64 + (lane >> 2);
        const int kk = lane & 3;
#pragma unroll
        for (int i = 0; i < 4; i++)
#pragma unroll
            for (int ks = 0; ks < 2; ks++) {
                const float* base = &Xs[(ar + i * 16) * EST + ks * 8 + kk];
                ya[i][ks][0] = __float_as_uint(base[0]);
                ya[i][ks][1] = __float_as_uint(base[8 * EST]);
                ya[i][ks][2] = __float_as_uint(base[4]);
                ya[i][ks][3] = __float_as_uint(base[8 * EST + 4]);
            }

        float* outh = out + (size_t)h * ((size_t)MTOT * OK);
#pragma unroll
        for (int j = 0; j < 4; j++) {
            uint32_t yb[2][2];
            const int bn = wn * 32 + j * 8 + (lane >> 2);
#pragma unroll
            for (int ks = 0; ks < 2; ks++) {
                const float* base = &Ws[bn * EST + ks * 8 + kk];
                yb[ks][0] = __float_as_uint(base[0]);
                yb[ks][1] = __float_as_uint(base[4]);
            }
            const int colb = n0 + wn * 32 + j * 8 + (lane & 3) * 2;
#pragma unroll
            for (int i = 0; i < 4; i++) {
                float corr[4];
                mma_tf32_dc(corr, c[i][j], ya[i][0], yb[0]);
                mma_tf32(corr, ya[i][1], yb[1]);
                const int r0 = m0 + wm * 64 + i * 16 + (lane >> 2);
                *reinterpret_cast<float2*>(outh + (size_t)r0 * OK + colb) =
                    make_float2(corr[0], corr[1]);
                *reinterpret_cast<float2*>(outh + (size_t)(r0 + 8) * OK + colb) =
                    make_float2(corr[2], corr[3]);
            }
        }
    }
}

// ---------------------------------------------------------------------------

extern "C" void kernel_launch(void* const* d_in, const int* in_sizes, int n_in,
                              void* d_out, int out_size) {
    const float* x           = (const float*)d_in[0];
    const float* W           = (const float*)d_in[1];
    const float* b           = (const float*)d_in[2];
    const float* A_sh        = (const float*)d_in[3];
    const float* B_sh        = (const float*)d_in[4];
    const float* A_tasks     = (const float*)d_in[5];
    const float* B_tasks     = (const float*)d_in[6];
    const float* task_scales = (const float*)d_in[7];
    float* out = (float*)d_out;

    (void)in_sizes; (void)n_in; (void)out_size;

    lora_y_kernel<<<dim3(MTOT / BM), 256>>>(x, A_sh, A_tasks);
    fused_main<<<dim3(OK / BN, MTOT / BM), 256>>>(x, W, b, B_sh, B_tasks, task_scales, out);
}

// round 3
// speedup vs baseline: 1.0190x; 1.0190x over previous
#include <cuda_runtime.h>
#include <cuda_bf16.h>
#include <cstdint>

// ===========================================================================
// MTLoRALinear on sm_103a — legacy-tensor-pipe optimized (tcgen05 unavailable
// through this harness's compute_103 PTX path).
//   prep_x / prep_wk : fp32 -> bf16 hi/lo split globals
//   lora_y  : Y[M,80] = x @ concat(A_sh, A_tasks)^T  (tf32 mma.sync, validated)
//   fused   : P = x@W^T via 3-term bf16 m16n8k16 mma (hh+hl+lh), cp.async
//             4-stage pipeline + ldmatrix; epilogue stages Y/B once and runs
//             5 per-head rank-16 tf32 corrections back-to-back.
// ===========================================================================

namespace {
constexpr int MTOT = 32768, DK = 1024, OK = 1024;
constexpr int BM = 128, BN = 128, BK = 32;
constexpr int NCHUNK = DK / BK;           // 32
constexpr int NSTAGE = 4;
constexpr int TILE_B = 8192;              // one 128x32 bf16 tile
constexpr int STAGE_B = 4 * TILE_B;       // Xhi|Xlo|Whi|Wlo = 32KB
constexpr int SMEM_DYN = NSTAGE * STAGE_B + 1024;   // +align slack
constexpr int EPI_B_OFF = 45056;          // Bs float tile offset in smem
constexpr int XST = 36;                   // lora_y smem stride
constexpr int EST = 84;                   // epilogue stride (84%32=20 -> conflict-free)
}

__device__ __align__(256) __nv_bfloat16 g_xhi[MTOT * DK];
__device__ __align__(256) __nv_bfloat16 g_xlo[MTOT * DK];
__device__ __align__(256) __nv_bfloat16 g_whi[OK * DK];
__device__ __align__(256) __nv_bfloat16 g_wlo[OK * DK];
__device__ __align__(256) float         g_Y[MTOT * 80];

// --------------------------- helpers ---------------------------------------
__device__ __forceinline__ uint32_t smem_u32(const void* p) {
    uint32_t a;
    asm("{ .reg .u64 t; cvta.to.shared.u64 t, %1; cvt.u32.u64 %0, t; }"
        : "=r"(a) : "l"(p));
    return a;
}
__device__ __forceinline__ void cp16(uint32_t dst, const void* src) {
    asm volatile("cp.async.cg.shared.global [%0], [%1], 16;"
                 :: "r"(dst), "l"(src) : "memory");
}
__device__ __forceinline__ void cp_commit() {
    asm volatile("cp.async.commit_group;" ::: "memory");
}
template <int N> __device__ __forceinline__ void cp_wait() {
    asm volatile("cp.async.wait_group %0;" :: "n"(N) : "memory");
}
__device__ __forceinline__ void ldsm4(uint32_t& r0, uint32_t& r1, uint32_t& r2,
                                      uint32_t& r3, uint32_t a) {
    asm volatile("ldmatrix.sync.aligned.m8n8.x4.shared.b16 {%0,%1,%2,%3}, [%4];"
                 : "=r"(r0), "=r"(r1), "=r"(r2), "=r"(r3) : "r"(a));
}
__device__ __forceinline__ void ldsm2(uint32_t& r0, uint32_t& r1, uint32_t a) {
    asm volatile("ldmatrix.sync.aligned.m8n8.x2.shared.b16 {%0,%1}, [%2];"
                 : "=r"(r0), "=r"(r1) : "r"(a));
}
__device__ __forceinline__ void mma_bf16(float* c, const uint32_t* a,
                                         const uint32_t* b) {
    asm volatile(
        "mma.sync.aligned.m16n8k16.row.col.f32.bf16.bf16.f32 "
        "{%0,%1,%2,%3}, {%4,%5,%6,%7}, {%8,%9}, {%0,%1,%2,%3};"
        : "+f"(c[0]), "+f"(c[1]), "+f"(c[2]), "+f"(c[3])
        : "r"(a[0]), "r"(a[1]), "r"(a[2]), "r"(a[3]), "r"(b[0]), "r"(b[1]));
}
__device__ __forceinline__ uint32_t tf32_rna(float x) {
    uint32_t u;
    asm("cvt.rna.tf32.f32 %0, %1;" : "=r"(u) : "f"(x));
    return u;
}
__device__ __forceinline__ float tf32f(float x) {
    return __uint_as_float(tf32_rna(x));
}
__device__ __forceinline__ void mma_tf32(float* c, const uint32_t* a,
                                         const uint32_t* b) {
    asm volatile(
        "mma.sync.aligned.m16n8k8.row.col.f32.tf32.tf32.f32 "
        "{%0,%1,%2,%3}, {%4,%5,%6,%7}, {%8,%9}, {%0,%1,%2,%3};"
        : "+f"(c[0]), "+f"(c[1]), "+f"(c[2]), "+f"(c[3])
        : "r"(a[0]), "r"(a[1]), "r"(a[2]), "r"(a[3]), "r"(b[0]), "r"(b[1]));
}
__device__ __forceinline__ void mma_tf32_dc(float* d, const float* c,
                                            const uint32_t* a, const uint32_t* b) {
    asm volatile(
        "mma.sync.aligned.m16n8k8.row.col.f32.tf32.tf32.f32 "
        "{%0,%1,%2,%3}, {%4,%5,%6,%7}, {%8,%9}, {%10,%11,%12,%13};"
        : "=f"(d[0]), "=f"(d[1]), "=f"(d[2]), "=f"(d[3])
        : "r"(a[0]), "r"(a[1]), "r"(a[2]), "r"(a[3]), "r"(b[0]), "r"(b[1]),
          "f"(c[0]), "f"(c[1]), "f"(c[2]), "f"(c[3]));
}
// hi/lo bf16 split of 8 fp32, packed k-ascending
__device__ __forceinline__ void split8(const float4& a, const float4& b,
                                       uint4& h, uint4& l) {
    float f[8] = {a.x, a.y, a.z, a.w, b.x, b.y, b.z, b.w};
    uint32_t hp[4], lp[4];
#pragma unroll
    for (int i = 0; i < 4; i++) {
        __nv_bfloat16 h0 = __float2bfloat16_rn(f[2 * i]);
        __nv_bfloat16 h1 = __float2bfloat16_rn(f[2 * i + 1]);
        __nv_bfloat16 l0 = __float2bfloat16_rn(f[2 * i] - __bfloat162float(h0));
        __nv_bfloat16 l1 = __float2bfloat16_rn(f[2 * i + 1] - __bfloat162float(h1));
        hp[i] = (uint32_t)__bfloat16_as_ushort(h0) |
                ((uint32_t)__bfloat16_as_ushort(h1) << 16);
        lp[i] = (uint32_t)__bfloat16_as_ushort(l0) |
                ((uint32_t)__bfloat16_as_ushort(l1) << 16);
    }
    h = make_uint4(hp[0], hp[1], hp[2], hp[3]);
    l = make_uint4(lp[0], lp[1], lp[2], lp[3]);
}
// smem byte offset within a 128x32 bf16 tile (64B rows, XOR-16B swizzle)
__device__ __forceinline__ uint32_t tswz(int row, int chunk) {
    return (uint32_t)(row * 64 + ((chunk ^ ((row >> 1) & 3)) << 4));
}

// --------------------------- prep kernels ----------------------------------
__global__ __launch_bounds__(256) void prep_x(const float* __restrict__ x) {
    size_t i = ((size_t)blockIdx.x * 256 + threadIdx.x) * 8;
    float4 a = *reinterpret_cast<const float4*>(x + i);
    float4 b = *reinterpret_cast<const float4*>(x + i + 4);
    uint4 h, l;
    split8(a, b, h, l);
    *reinterpret_cast<uint4*>(g_xhi + i) = h;
    *reinterpret_cast<uint4*>(g_xlo + i) = l;
}
__global__ __launch_bounds__(256) void prep_wk(const float* __restrict__ W) {
    size_t i = ((size_t)blockIdx.x * 256 + threadIdx.x) * 8;
    float4 a = *reinterpret_cast<const float4*>(W + i);
    float4 b = *reinterpret_cast<const float4*>(W + i + 4);
    uint4 h, l;
    split8(a, b, h, l);
    *reinterpret_cast<uint4*>(g_whi + i) = h;
    *reinterpret_cast<uint4*>(g_wlo + i) = l;
}

// ------------------- lora_y (validated tf32 path) --------------------------
__global__ __launch_bounds__(256) void lora_y_kernel(
    const float* __restrict__ x,
    const float* __restrict__ A_sh,
    const float* __restrict__ A_tasks)
{
    __shared__ float Xs[BM * XST];
    __shared__ float Ws[BM * XST];

    const int tid = threadIdx.x;
    const int lane = tid & 31, wid = tid >> 5;
    const int wm = wid >> 2, wn = wid & 3;
    const int m0 = blockIdx.x * BM;
    const int lr = tid >> 3;
    const int lc = (tid & 7) << 2;

    const float* xg = x + (size_t)(m0 + lr) * DK + lc;
    const float* ag[4];
    bool av[4];
#pragma unroll
    for (int i = 0; i < 4; i++) {
        const int r = lr + 32 * i;
        if (r < 16)      { ag[i] = A_sh + (size_t)r * DK + lc; av[i] = true; }
        else if (r < 80) { ag[i] = A_tasks + (size_t)(r - 16) * DK + lc; av[i] = true; }
        else             { ag[i] = A_sh + lc; av[i] = false; }
    }

    float4 px[4], pw[4];
    const float4 z4 = make_float4(0.f, 0.f, 0.f, 0.f);
#pragma unroll
    for (int i = 0; i < 4; i++) {
        px[i] = *reinterpret_cast<const float4*>(xg + (size_t)(32 * i) * DK);
        pw[i] = av[i] ? *reinterpret_cast<const float4*>(ag[i]) : z4;
    }

    float c[4][4][4];
#pragma unroll
    for (int i = 0; i < 4; i++)
#pragma unroll
        for (int j = 0; j < 4; j++)
#pragma unroll
            for (int q = 0; q < 4; q++) c[i][j][q] = 0.f;

    for (int kc = 0; kc < DK; kc += 32) {
        __syncthreads();
#pragma unroll
        for (int i = 0; i < 4; i++) {
            float* xs = &Xs[(lr + 32 * i) * XST + lc];
            xs[0] = tf32f(px[i].x); xs[1] = tf32f(px[i].y);
            xs[2] = tf32f(px[i].z); xs[3] = tf32f(px[i].w);
            float* ws = &Ws[(lr + 32 * i) * XST + lc];
            ws[0] = tf32f(pw[i].x); ws[1] = tf32f(pw[i].y);
            ws[2] = tf32f(pw[i].z); ws[3] = tf32f(pw[i].w);
        }
        __syncthreads();
        if (kc + 32 < DK) {
#pragma unroll
            for (int i = 0; i < 4; i++) {
                px[i] = *reinterpret_cast<const float4*>(xg + (size_t)(32 * i) * DK + kc + 32);
                pw[i] = av[i] ? *reinterpret_cast<const float4*>(ag[i] + kc + 32) : z4;
            }
        }
#pragma unroll
        for (int ks = 0; ks < 4; ks++) {
            const int ak = ks * 8 + (lane & 3);
            const int ar = wm * 64 + (lane >> 2);
            uint32_t a[4][4];
#pragma unroll
            for (int i = 0; i < 4; i++) {
                const float* base = &Xs[(ar + i * 16) * XST + ak];
                a[i][0] = __float_as_uint(base[0]);
                a[i][1] = __float_as_uint(base[8 * XST]);
                a[i][2] = __float_as_uint(base[4]);
                a[i][3] = __float_as_uint(base[8 * XST + 4]);
            }
            uint32_t b[4][2];
            const int bn = wn * 32 + (lane >> 2);
#pragma unroll
            for (int j = 0; j < 4; j++) {
                const float* base = &Ws[(bn + j * 8) * XST + ak];
                b[j][0] = __float_as_uint(base[0]);
                b[j][1] = __float_as_uint(base[4]);
            }
#pragma unroll
            for (int i = 0; i < 4; i++)
#pragma unroll
                for (int j = 0; j < 4; j++)
                    mma_tf32(c[i][j], a[i], b[j]);
        }
    }

#pragma unroll
    for (int j = 0; j < 4; j++) {
        const int colb = wn * 32 + j * 8 + (lane & 3) * 2;
        if (colb < 80) {
#pragma unroll
            for (int i = 0; i < 4; i++) {
                const int r0 = m0 + wm * 64 + i * 16 + (lane >> 2);
                *reinterpret_cast<float2*>(g_Y + (size_t)r0 * 80 + colb) =
                    make_float2(c[i][j][0], c[i][j][1]);
                *reinterpret_cast<float2*>(g_Y + (size_t)(r0 + 8) * 80 + colb) =
                    make_float2(c[i][j][2], c[i][j][3]);
            }
        }
    }
}

// --------------------------- fused main ------------------------------------
__global__ __launch_bounds__(256, 1) void fused_main(
    const float* __restrict__ bias,
    const float* __restrict__ B_sh,
    const float* __restrict__ B_tasks,
    const float* __restrict__ task_scales,
    float* __restrict__ out)
{
    extern __shared__ char dsm[];
    const uint32_t raw = smem_u32(dsm);
    const uint32_t base = (raw + 1023u) & ~1023u;
    char* sm = dsm + (base - raw);

    const int tid = threadIdx.x, wid = tid >> 5, lane = tid & 31;
    const int wm = wid >> 2, wn = wid & 3;
    const int m0 = blockIdx.y * BM, n0 = blockIdx.x * BN;

    // ---- cp.async source/dst precompute: 8 chunks of 16B per thread -------
    const __nv_bfloat16* srcb[8];
    uint32_t dsto[8];
#pragma unroll
    for (int p = 0; p < 8; p++) {
        const int id = p * 256 + tid;           // 0..2047
        const int tile = id >> 9;               // 0..3  (xhi,xlo,whi,wlo)
        const int within = id & 511;
        const int row = within >> 2;
        const int ch = within & 3;
        dsto[p] = (uint32_t)(tile << 13) + tswz(row, ch);
        const __nv_bfloat16* g =
            (tile == 0) ? g_xhi : (tile == 1) ? g_xlo :
            (tile == 2) ? g_whi : g_wlo;
        const int grow = (tile < 2 ? m0 : n0) + row;
        srcb[p] = g + (size_t)grow * DK + ch * 8;
    }
    auto issue = [&](int chunk) {
        const uint32_t sb = base + (chunk & (NSTAGE - 1)) * STAGE_B;
#pragma unroll
        for (int p = 0; p < 8; p++)
            cp16(sb + dsto[p], srcb[p] + chunk * BK);
        cp_commit();
    };

    issue(0); issue(1); issue(2);

    float c[4][4][4];
#pragma unroll
    for (int i = 0; i < 4; i++)
#pragma unroll
        for (int j = 0; j < 4; j++)
#pragma unroll
            for (int q = 0; q < 4; q++) c[i][j][q] = 0.f;

    // ldmatrix per-lane address components
    const int qrow = lane & 7, q = lane >> 3;
    const int a_row_off = wm * 64 + (q & 1) * 8 + qrow;  // + i*16
    const int a_ch_off = q >> 1;                         // + ks*2
    const int b_row_off = wn * 32 + (lane & 7);          // + j*8 (lanes 0-15)
    const int b_ch_off = (lane >> 3) & 1;                // + ks*2

    for (int it = 0; it < NCHUNK; it++) {
        cp_wait<2>();
        __syncthreads();
        const uint32_t sb = base + (it & (NSTAGE - 1)) * STAGE_B;
#pragma unroll
        for (int ks = 0; ks < 2; ks++) {
            uint32_t ahi[4][4], alo[4][4];
#pragma unroll
            for (int i = 0; i < 4; i++) {
                const int row = a_row_off + i * 16;
                const uint32_t o = tswz(row, ks * 2 + a_ch_off);
                ldsm4(ahi[i][0], ahi[i][1], ahi[i][2], ahi[i][3], sb + o);
                ldsm4(alo[i][0], alo[i][1], alo[i][2], alo[i][3],
                      sb + TILE_B + o);
            }
#pragma unroll
            for (int j = 0; j < 4; j++) {
                const int row = b_row_off + j * 8;
                const uint32_t o = tswz(row, ks * 2 + b_ch_off);
                uint32_t bhi[2], blo[2];
                ldsm2(bhi[0], bhi[1], sb + 2 * TILE_B + o);
                ldsm2(blo[0], blo[1], sb + 3 * TILE_B + o);
#pragma unroll
                for (int i = 0; i < 4; i++) {
                    mma_bf16(c[i][j], ahi[i], bhi);
                    mma_bf16(c[i][j], ahi[i], blo);
                    mma_bf16(c[i][j], alo[i], bhi);
                }
            }
        }
        if (it + 3 < NCHUNK) issue(it + 3);
        else cp_commit();   // keep wait_group bookkeeping uniform
    }
    cp_wait<0>();
    __syncthreads();

    // ---- bias ------------------------------------------------------------
#pragma unroll
    for (int j = 0; j < 4; j++) {
        const int col = n0 + wn * 32 + j * 8 + (lane & 3) * 2;
        const float b0 = __ldg(bias + col);
        const float b1 = __ldg(bias + col + 1);
#pragma unroll
        for (int i = 0; i < 4; i++) {
            c[i][j][0] += b0; c[i][j][1] += b1;
            c[i][j][2] += b0; c[i][j][3] += b1;
        }
    }

    // ---- epilogue: stage Y[128x80] and scaled B_all[128x80] once ----------
    float* Ys = reinterpret_cast<float*>(sm);
    float* Bs = reinterpret_cast<float*>(sm + EPI_B_OFF);
    {
        const int srow = tid >> 1, half = tid & 1;
        const float* ys = g_Y + (size_t)(m0 + srow) * 80 + half * 40;
        float* yd = Ys + srow * EST + half * 40;
#pragma unroll
        for (int g = 0; g < 10; g++) {
            float4 v = __ldg(reinterpret_cast<const float4*>(ys + g * 4));
            yd[g * 4 + 0] = tf32f(v.x); yd[g * 4 + 1] = tf32f(v.y);
            yd[g * 4 + 2] = tf32f(v.z); yd[g * 4 + 3] = tf32f(v.w);
        }
        float sc[4];
#pragma unroll
        for (int t = 0; t < 4; t++) sc[t] = __ldg(task_scales + t);
        float* bd = Bs + srow * EST + half * 40;
#pragma unroll
        for (int g = 0; g < 10; g++) {
            const int k0 = half * 40 + g * 4;
            const float* src;
            float s;
            if (k0 < 16) { src = B_sh + (size_t)(n0 + srow) * 16 + k0; s = 1.f; }
            else {
                const int t = (k0 - 16) >> 4, rr = (k0 - 16) & 15;
                src = B_tasks + ((size_t)t * OK + n0 + srow) * 16 + rr;
                s = sc[t];
            }
            float4 v = __ldg(reinterpret_cast<const float4*>(src));
            bd[g * 4 + 0] = tf32f(v.x * s); bd[g * 4 + 1] = tf32f(v.y * s);
            bd[g * 4 + 2] = tf32f(v.z * s); bd[g * 4 + 3] = tf32f(v.w * s);
        }
    }
    __syncthreads();

    const int ar = wm * 64 + (lane >> 2);
    const int kk = lane & 3;
    for (int h = 0; h < 5; h++) {
        uint32_t ya[4][2][4];
#pragma unroll
        for (int i = 0; i < 4; i++)
#pragma unroll
            for (int ks = 0; ks < 2; ks++) {
                const float* bp = &Ys[(ar + i * 16) * EST + h * 16 + ks * 8 + kk];
                ya[i][ks][0] = __float_as_uint(bp[0]);
                ya[i][ks][1] = __float_as_uint(bp[8 * EST]);
                ya[i][ks][2] = __float_as_uint(bp[4]);
                ya[i][ks][3] = __float_as_uint(bp[8 * EST + 4]);
            }
        float* outh = out + (size_t)h * MTOT * OK;
#pragma unroll
        for (int j = 0; j < 4; j++) {
            uint32_t yb[2][2];
            const int bn = wn * 32 + j * 8 + (lane >> 2);
#pragma unroll
            for (int ks = 0; ks < 2; ks++) {
                const float* bp = &Bs[bn * EST + h * 16 + ks * 8 + kk];
                yb[ks][0] = __float_as_uint(bp[0]);
                yb[ks][1] = __float_as_uint(bp[4]);
            }
            const int colb = n0 + wn * 32 + j * 8 + (lane & 3) * 2;
#pragma unroll
            for (int i = 0; i < 4; i++) {
                float corr[4];
                mma_tf32_dc(corr, c[i][j], ya[i][0], yb[0]);
                mma_tf32(corr, ya[i][1], yb[1]);
                const int r0 = m0 + wm * 64 + i * 16 + (lane >> 2);
                *reinterpret_cast<float2*>(outh + (size_t)r0 * OK + colb) =
                    make_float2(corr[0], corr[1]);
                *reinterpret_cast<float2*>(outh + (size_t)(r0 + 8) * OK + colb) =
                    make_float2(corr[2], corr[3]);
            }
        }
    }
}

// ---------------------------------------------------------------------------
extern "C" void kernel_launch(void* const* d_in, const int* in_sizes, int n_in,
                              void* d_out, int out_size) {
    const float* x           = (const float*)d_in[0];
    const float* W           = (const float*)d_in[1];
    const float* b           = (const float*)d_in[2];
    const float* A_sh        = (const float*)d_in[3];
    const float* B_sh        = (const float*)d_in[4];
    const float* A_tasks     = (const float*)d_in[5];
    const float* B_tasks     = (const float*)d_in[6];
    const float* task_scales = (const float*)d_in[7];
    float* out = (float*)d_out;
    (void)in_sizes; (void)n_in; (void)out_size;

    cudaFuncSetAttribute(fused_main, cudaFuncAttributeMaxDynamicSharedMemorySize,
                         SMEM_DYN);

    prep_x<<<MTOT * DK / 2048, 256>>>(x);
    prep_wk<<<OK * DK / 2048, 256>>>(W);
    lora_y_kernel<<<MTOT / BM, 256>>>(x, A_sh, A_tasks);
    fused_main<<<dim3(OK / BN, MTOT / BM), 256, SMEM_DYN>>>(
        b, B_sh, B_tasks, task_scales, out);
}

// round 4
// speedup vs baseline: 1.0956x; 1.0751x over previous
#include <cuda_runtime.h>
#include <cuda_bf16.h>
#include <cstdint>

// ===========================================================================
// MTLoRALinear on sm_103a — legacy-tensor-pipe (tcgen05 blocked by harness
// compute_103 PTX path).
//   prep_wk : W fp32 -> bf16 hi/lo
//   lora_y  : Y[M,80] = x @ concat(A_sh,A_tasks)^T (tf32) AND x -> bf16 hi/lo
//   fused   : P = x@W^T via 3-term bf16 m16n8k16 mma (hh+hl+lh), BK=64,
//             cp.async 3-stage pipeline + ldmatrix; epilogue: 5 rank-16
//             tf32 corrections + streamed stores.
// ===========================================================================

namespace {
constexpr int MTOT = 32768, DK = 1024, OK = 1024;
constexpr int BM = 128, BN = 128, BK = 64;
constexpr int NCHUNK = DK / BK;           // 16
constexpr int NSTAGE = 3;
constexpr int TILE_B = 16384;             // one 128x64 bf16 tile
constexpr int STAGE_B = 4 * TILE_B;       // Xhi|Xlo|Whi|Wlo = 64KB
constexpr int SMEM_DYN = NSTAGE * STAGE_B + 1024;   // 197632
constexpr int EPI_B_OFF = 45056;
constexpr int XST = 36;                   // lora_y smem stride
constexpr int EST = 84;                   // epilogue stride (conflict-free)
}

__device__ __align__(256) __nv_bfloat16 g_xhi[MTOT * DK];
__device__ __align__(256) __nv_bfloat16 g_xlo[MTOT * DK];
__device__ __align__(256) __nv_bfloat16 g_whi[OK * DK];
__device__ __align__(256) __nv_bfloat16 g_wlo[OK * DK];
__device__ __align__(256) float         g_Y[MTOT * 80];

// --------------------------- helpers ---------------------------------------
__device__ __forceinline__ uint32_t smem_u32(const void* p) {
    uint32_t a;
    asm("{ .reg .u64 t; cvta.to.shared.u64 t, %1; cvt.u32.u64 %0, t; }"
        : "=r"(a) : "l"(p));
    return a;
}
__device__ __forceinline__ void cp16(uint32_t dst, const void* src) {
    asm volatile("cp.async.cg.shared.global [%0], [%1], 16;"
                 :: "r"(dst), "l"(src) : "memory");
}
__device__ __forceinline__ void cp_commit() {
    asm volatile("cp.async.commit_group;" ::: "memory");
}
template <int N> __device__ __forceinline__ void cp_wait() {
    asm volatile("cp.async.wait_group %0;" :: "n"(N) : "memory");
}
__device__ __forceinline__ void ldsm4(uint32_t& r0, uint32_t& r1, uint32_t& r2,
                                      uint32_t& r3, uint32_t a) {
    asm volatile("ldmatrix.sync.aligned.m8n8.x4.shared.b16 {%0,%1,%2,%3}, [%4];"
                 : "=r"(r0), "=r"(r1), "=r"(r2), "=r"(r3) : "r"(a));
}
__device__ __forceinline__ void ldsm2(uint32_t& r0, uint32_t& r1, uint32_t a) {
    asm volatile("ldmatrix.sync.aligned.m8n8.x2.shared.b16 {%0,%1}, [%2];"
                 : "=r"(r0), "=r"(r1) : "r"(a));
}
__device__ __forceinline__ void mma_bf16(float* c, const uint32_t* a,
                                         const uint32_t* b) {
    asm volatile(
        "mma.sync.aligned.m16n8k16.row.col.f32.bf16.bf16.f32 "
        "{%0,%1,%2,%3}, {%4,%5,%6,%7}, {%8,%9}, {%0,%1,%2,%3};"
        : "+f"(c[0]), "+f"(c[1]), "+f"(c[2]), "+f"(c[3])
        : "r"(a[0]), "r"(a[1]), "r"(a[2]), "r"(a[3]), "r"(b[0]), "r"(b[1]));
}
__device__ __forceinline__ uint32_t tf32_rna(float x) {
    uint32_t u;
    asm("cvt.rna.tf32.f32 %0, %1;" : "=r"(u) : "f"(x));
    return u;
}
__device__ __forceinline__ float tf32f(float x) {
    return __uint_as_float(tf32_rna(x));
}
__device__ __forceinline__ void mma_tf32(float* c, const uint32_t* a,
                                         const uint32_t* b) {
    asm volatile(
        "mma.sync.aligned.m16n8k8.row.col.f32.tf32.tf32.f32 "
        "{%0,%1,%2,%3}, {%4,%5,%6,%7}, {%8,%9}, {%0,%1,%2,%3};"
        : "+f"(c[0]), "+f"(c[1]), "+f"(c[2]), "+f"(c[3])
        : "r"(a[0]), "r"(a[1]), "r"(a[2]), "r"(a[3]), "r"(b[0]), "r"(b[1]));
}
__device__ __forceinline__ void mma_tf32_dc(float* d, const float* c,
                                            const uint32_t* a, const uint32_t* b) {
    asm volatile(
        "mma.sync.aligned.m16n8k8.row.col.f32.tf32.tf32.f32 "
        "{%0,%1,%2,%3}, {%4,%5,%6,%7}, {%8,%9}, {%10,%11,%12,%13};"
        : "=f"(d[0]), "=f"(d[1]), "=f"(d[2]), "=f"(d[3])
        : "r"(a[0]), "r"(a[1]), "r"(a[2]), "r"(a[3]), "r"(b[0]), "r"(b[1]),
          "f"(c[0]), "f"(c[1]), "f"(c[2]), "f"(c[3]));
}
__device__ __forceinline__ void split8(const float4& a, const float4& b,
                                       uint4& h, uint4& l) {
    float f[8] = {a.x, a.y, a.z, a.w, b.x, b.y, b.z, b.w};
    uint32_t hp[4], lp[4];
#pragma unroll
    for (int i = 0; i < 4; i++) {
        __nv_bfloat16 h0 = __float2bfloat16_rn(f[2 * i]);
        __nv_bfloat16 h1 = __float2bfloat16_rn(f[2 * i + 1]);
        __nv_bfloat16 l0 = __float2bfloat16_rn(f[2 * i] - __bfloat162float(h0));
        __nv_bfloat16 l1 = __float2bfloat16_rn(f[2 * i + 1] - __bfloat162float(h1));
        hp[i] = (uint32_t)__bfloat16_as_ushort(h0) |
                ((uint32_t)__bfloat16_as_ushort(h1) << 16);
        lp[i] = (uint32_t)__bfloat16_as_ushort(l0) |
                ((uint32_t)__bfloat16_as_ushort(l1) << 16);
    }
    h = make_uint4(hp[0], hp[1], hp[2], hp[3]);
    l = make_uint4(lp[0], lp[1], lp[2], lp[3]);
}
__device__ __forceinline__ void split4(const float4& v, uint2& h, uint2& l) {
    __nv_bfloat16 h0 = __float2bfloat16_rn(v.x), h1 = __float2bfloat16_rn(v.y);
    __nv_bfloat16 h2 = __float2bfloat16_rn(v.z), h3 = __float2bfloat16_rn(v.w);
    __nv_bfloat16 l0 = __float2bfloat16_rn(v.x - __bfloat162float(h0));
    __nv_bfloat16 l1 = __float2bfloat16_rn(v.y - __bfloat162float(h1));
    __nv_bfloat16 l2 = __float2bfloat16_rn(v.z - __bfloat162float(h2));
    __nv_bfloat16 l3 = __float2bfloat16_rn(v.w - __bfloat162float(h3));
    h.x = (uint32_t)__bfloat16_as_ushort(h0) | ((uint32_t)__bfloat16_as_ushort(h1) << 16);
    h.y = (uint32_t)__bfloat16_as_ushort(h2) | ((uint32_t)__bfloat16_as_ushort(h3) << 16);
    l.x = (uint32_t)__bfloat16_as_ushort(l0) | ((uint32_t)__bfloat16_as_ushort(l1) << 16);
    l.y = (uint32_t)__bfloat16_as_ushort(l2) | ((uint32_t)__bfloat16_as_ushort(l3) << 16);
}
// 128x64 bf16 tile: 128B rows, 8x16B chunks, XOR-8 swizzle
__device__ __forceinline__ uint32_t tswz(int row, int ch) {
    return (uint32_t)(row * 128 + ((ch ^ (row & 7)) << 4));
}

// --------------------------- prep W ----------------------------------------
__global__ __launch_bounds__(256) void prep_wk(const float* __restrict__ W) {
    size_t i = ((size_t)blockIdx.x * 256 + threadIdx.x) * 8;
    float4 a = *reinterpret_cast<const float4*>(W + i);
    float4 b = *reinterpret_cast<const float4*>(W + i + 4);
    uint4 h, l;
    split8(a, b, h, l);
    *reinterpret_cast<uint4*>(g_whi + i) = h;
    *reinterpret_cast<uint4*>(g_wlo + i) = l;
}

// ---------------- lora_y + inline x -> bf16 hi/lo split --------------------
__global__ __launch_bounds__(256) void lora_y_kernel(
    const float* __restrict__ x,
    const float* __restrict__ A_sh,
    const float* __restrict__ A_tasks)
{
    __shared__ float Xs[BM * XST];
    __shared__ float Ws[BM * XST];

    const int tid = threadIdx.x;
    const int lane = tid & 31, wid = tid >> 5;
    const int wm = wid >> 2, wn = wid & 3;
    const int m0 = blockIdx.x * BM;
    const int lr = tid >> 3;
    const int lc = (tid & 7) << 2;

    const float* xg = x + (size_t)(m0 + lr) * DK + lc;
    const float* ag[4];
    bool av[4];
#pragma unroll
    for (int i = 0; i < 4; i++) {
        const int r = lr + 32 * i;
        if (r < 16)      { ag[i] = A_sh + (size_t)r * DK + lc; av[i] = true; }
        else if (r < 80) { ag[i] = A_tasks + (size_t)(r - 16) * DK + lc; av[i] = true; }
        else             { ag[i] = A_sh + lc; av[i] = false; }
    }

    float4 px[4], pw[4];
    const float4 z4 = make_float4(0.f, 0.f, 0.f, 0.f);
#pragma unroll
    for (int i = 0; i < 4; i++) {
        px[i] = *reinterpret_cast<const float4*>(xg + (size_t)(32 * i) * DK);
        pw[i] = av[i] ? *reinterpret_cast<const float4*>(ag[i]) : z4;
    }

    float c[4][4][4];
#pragma unroll
    for (int i = 0; i < 4; i++)
#pragma unroll
        for (int j = 0; j < 4; j++)
#pragma unroll
            for (int q = 0; q < 4; q++) c[i][j][q] = 0.f;

    for (int kc = 0; kc < DK; kc += 32) {
        __syncthreads();
#pragma unroll
        for (int i = 0; i < 4; i++) {
            // side product: x -> bf16 hi/lo (each element written exactly once)
            {
                uint2 h, l;
                split4(px[i], h, l);
                const size_t go = (size_t)(m0 + lr + 32 * i) * DK + kc + lc;
                *reinterpret_cast<uint2*>(g_xhi + go) = h;
                *reinterpret_cast<uint2*>(g_xlo + go) = l;
            }
            float* xs = &Xs[(lr + 32 * i) * XST + lc];
            xs[0] = tf32f(px[i].x); xs[1] = tf32f(px[i].y);
            xs[2] = tf32f(px[i].z); xs[3] = tf32f(px[i].w);
            float* ws = &Ws[(lr + 32 * i) * XST + lc];
            ws[0] = tf32f(pw[i].x); ws[1] = tf32f(pw[i].y);
            ws[2] = tf32f(pw[i].z); ws[3] = tf32f(pw[i].w);
        }
        __syncthreads();
        if (kc + 32 < DK) {
#pragma unroll
            for (int i = 0; i < 4; i++) {
                px[i] = *reinterpret_cast<const float4*>(xg + (size_t)(32 * i) * DK + kc + 32);
                pw[i] = av[i] ? *reinterpret_cast<const float4*>(ag[i] + kc + 32) : z4;
            }
        }
#pragma unroll
        for (int ks = 0; ks < 4; ks++) {
            const int ak = ks * 8 + (lane & 3);
            const int ar = wm * 64 + (lane >> 2);
            uint32_t a[4][4];
#pragma unroll
            for (int i = 0; i < 4; i++) {
                const float* base = &Xs[(ar + i * 16) * XST + ak];
                a[i][0] = __float_as_uint(base[0]);
                a[i][1] = __float_as_uint(base[8 * XST]);
                a[i][2] = __float_as_uint(base[4]);
                a[i][3] = __float_as_uint(base[8 * XST + 4]);
            }
            uint32_t b[4][2];
            const int bn = wn * 32 + (lane >> 2);
#pragma unroll
            for (int j = 0; j < 4; j++) {
                const float* base = &Ws[(bn + j * 8) * XST + ak];
                b[j][0] = __float_as_uint(base[0]);
                b[j][1] = __float_as_uint(base[4]);
            }
#pragma unroll
            for (int i = 0; i < 4; i++)
#pragma unroll
                for (int j = 0; j < 4; j++)
                    mma_tf32(c[i][j], a[i], b[j]);
        }
    }

#pragma unroll
    for (int j = 0; j < 4; j++) {
        const int colb = wn * 32 + j * 8 + (lane & 3) * 2;
        if (colb < 80) {
#pragma unroll
            for (int i = 0; i < 4; i++) {
                const int r0 = m0 + wm * 64 + i * 16 + (lane >> 2);
                *reinterpret_cast<float2*>(g_Y + (size_t)r0 * 80 + colb) =
                    make_float2(c[i][j][0], c[i][j][1]);
                *reinterpret_cast<float2*>(g_Y + (size_t)(r0 + 8) * 80 + colb) =
                    make_float2(c[i][j][2], c[i][j][3]);
            }
        }
    }
}

// --------------------------- fused main ------------------------------------
__global__ __launch_bounds__(256, 1) void fused_main(
    const float* __restrict__ bias,
    const float* __restrict__ B_sh,
    const float* __restrict__ B_tasks,
    const float* __restrict__ task_scales,
    float* __restrict__ out)
{
    extern __shared__ char dsm[];
    const uint32_t raw = smem_u32(dsm);
    const uint32_t base = (raw + 1023u) & ~1023u;
    char* sm = dsm + (base - raw);

    const int tid = threadIdx.x, wid = tid >> 5, lane = tid & 31;
    const int wm = wid >> 2, wn = wid & 3;
    const int m0 = blockIdx.y * BM, n0 = blockIdx.x * BN;

    // ---- cp.async: per-thread fixed (row-within-32, chunk) decomposition --
    // thread covers rows (tid>>3) + 32*pp, chunk column (tid&7), 4 tiles.
    const int trow = tid >> 3, tch = tid & 7;
    const uint32_t dbase = (uint32_t)(trow * 128 + ((tch ^ (trow & 7)) << 4));
    const __nv_bfloat16* tb[4];
    tb[0] = g_xhi + (size_t)(m0 + trow) * DK + tch * 8;
    tb[1] = g_xlo + (size_t)(m0 + trow) * DK + tch * 8;
    tb[2] = g_whi + (size_t)(n0 + trow) * DK + tch * 8;
    tb[3] = g_wlo + (size_t)(n0 + trow) * DK + tch * 8;

    uint32_t sb_issue[NSTAGE];
#pragma unroll
    for (int s = 0; s < NSTAGE; s++) sb_issue[s] = base + s * STAGE_B;

    auto issue = [&](int chunk, int stage) {
        const uint32_t sb = sb_issue[stage];
#pragma unroll
        for (int t = 0; t < 4; t++)
#pragma unroll
            for (int pp = 0; pp < 4; pp++)
                cp16(sb + (uint32_t)(t * TILE_B + pp * 4096) + dbase,
                     tb[t] + (size_t)pp * 32 * DK + chunk * BK);
        cp_commit();
    };

    issue(0, 0);
    issue(1, 1);

    float c[4][4][4];
#pragma unroll
    for (int i = 0; i < 4; i++)
#pragma unroll
        for (int j = 0; j < 4; j++)
#pragma unroll
            for (int q = 0; q < 4; q++) c[i][j][q] = 0.f;

    // ldmatrix per-lane address components
    const int qrow = lane & 7, q = lane >> 3;
    const int a_row_off = wm * 64 + (q & 1) * 8 + qrow;  // + i*16
    const int a_ch_off = q >> 1;                         // + ks*2
    const int b_row_off = wn * 32 + (lane & 7);          // + j*8
    const int b_ch_off = (lane >> 3) & 1;                // + ks*2

    int stage = 0;
    for (int it = 0; it < NCHUNK; it++) {
        cp_wait<1>();
        __syncthreads();
        // start next-next load right away (stage being overwritten was
        // consumed last iteration; the sync above fences it)
        {
            int ns = stage + 2; if (ns >= NSTAGE) ns -= NSTAGE;
            if (it + 2 < NCHUNK) issue(it + 2, ns);
            else cp_commit();
        }
        const uint32_t sb = base + stage * STAGE_B;
#pragma unroll
        for (int ks = 0; ks < 4; ks++) {
            uint32_t ahi[4][4], alo[4][4];
#pragma unroll
            for (int i = 0; i < 4; i++) {
                const int row = a_row_off + i * 16;
                const uint32_t o = tswz(row, ks * 2 + a_ch_off);
                ldsm4(ahi[i][0], ahi[i][1], ahi[i][2], ahi[i][3], sb + o);
                ldsm4(alo[i][0], alo[i][1], alo[i][2], alo[i][3],
                      sb + TILE_B + o);
            }
#pragma unroll
            for (int j = 0; j < 4; j++) {
                const int row = b_row_off + j * 8;
                const uint32_t o = tswz(row, ks * 2 + b_ch_off);
                uint32_t bhi[2], blo[2];
                ldsm2(bhi[0], bhi[1], sb + 2 * TILE_B + o);
                ldsm2(blo[0], blo[1], sb + 3 * TILE_B + o);
                // term-outer order: accumulator RAW chain distance = 4
#pragma unroll
                for (int i = 0; i < 4; i++) mma_bf16(c[i][j], ahi[i], bhi);
#pragma unroll
                for (int i = 0; i < 4; i++) mma_bf16(c[i][j], ahi[i], blo);
#pragma unroll
                for (int i = 0; i < 4; i++) mma_bf16(c[i][j], alo[i], bhi);
            }
        }
        if (++stage >= NSTAGE) stage -= NSTAGE;
    }
    cp_wait<0>();
    __syncthreads();

    // ---- bias ------------------------------------------------------------
#pragma unroll
    for (int j = 0; j < 4; j++) {
        const int col = n0 + wn * 32 + j * 8 + (lane & 3) * 2;
        const float b0 = __ldg(bias + col);
        const float b1 = __ldg(bias + col + 1);
#pragma unroll
        for (int i = 0; i < 4; i++) {
            c[i][j][0] += b0; c[i][j][1] += b1;
            c[i][j][2] += b0; c[i][j][3] += b1;
        }
    }

    // ---- epilogue: stage Y[128x80] and scaled B_all[128x80] once ----------
    float* Ys = reinterpret_cast<float*>(sm);
    float* Bs = reinterpret_cast<float*>(sm + EPI_B_OFF);
    {
        const int srow = tid >> 1, half = tid & 1;
        const float* ys = g_Y + (size_t)(m0 + srow) * 80 + half * 40;
        float* yd = Ys + srow * EST + half * 40;
#pragma unroll
        for (int g = 0; g < 10; g++) {
            float4 v = __ldg(reinterpret_cast<const float4*>(ys + g * 4));
            yd[g * 4 + 0] = tf32f(v.x); yd[g * 4 + 1] = tf32f(v.y);
            yd[g * 4 + 2] = tf32f(v.z); yd[g * 4 + 3] = tf32f(v.w);
        }
        float sc[4];
#pragma unroll
        for (int t = 0; t < 4; t++) sc[t] = __ldg(task_scales + t);
        float* bd = Bs + srow * EST + half * 40;
#pragma unroll
        for (int g = 0; g < 10; g++) {
            const int k0 = half * 40 + g * 4;
            const float* src;
            float s;
            if (k0 < 16) { src = B_sh + (size_t)(n0 + srow) * 16 + k0; s = 1.f; }
            else {
                const int t = (k0 - 16) >> 4, rr = (k0 - 16) & 15;
                src = B_tasks + ((size_t)t * OK + n0 + srow) * 16 + rr;
                s = sc[t];
            }
            float4 v = __ldg(reinterpret_cast<const float4*>(src));
            bd[g * 4 + 0] = tf32f(v.x * s); bd[g * 4 + 1] = tf32f(v.y * s);
            bd[g * 4 + 2] = tf32f(v.z * s); bd[g * 4 + 3] = tf32f(v.w * s);
        }
    }
    __syncthreads();

    const int ar = wm * 64 + (lane >> 2);
    const int kk = lane & 3;
    for (int h = 0; h < 5; h++) {
        uint32_t ya[4][2][4];
#pragma unroll
        for (int i = 0; i < 4; i++)
#pragma unroll
            for (int ks = 0; ks < 2; ks++) {
                const float* bp = &Ys[(ar + i * 16) * EST + h * 16 + ks * 8 + kk];
                ya[i][ks][0] = __float_as_uint(bp[0]);
                ya[i][ks][1] = __float_as_uint(bp[8 * EST]);
                ya[i][ks][2] = __float_as_uint(bp[4]);
                ya[i][ks][3] = __float_as_uint(bp[8 * EST + 4]);
            }
        float* outh = out + (size_t)h * MTOT * OK;
#pragma unroll
        for (int j = 0; j < 4; j++) {
            uint32_t yb[2][2];
            const int bn = wn * 32 + j * 8 + (lane >> 2);
#pragma unroll
            for (int ks = 0; ks < 2; ks++) {
                const float* bp = &Bs[bn * EST + h * 16 + ks * 8 + kk];
                yb[ks][0] = __float_as_uint(bp[0]);
                yb[ks][1] = __float_as_uint(bp[4]);
            }
            const int colb = n0 + wn * 32 + j * 8 + (lane & 3) * 2;
#pragma unroll
            for (int i = 0; i < 4; i++) {
                float corr[4];
                mma_tf32_dc(corr, c[i][j], ya[i][0], yb[0]);
                mma_tf32(corr, ya[i][1], yb[1]);
                const int r0 = m0 + wm * 64 + i * 16 + (lane >> 2);
                *reinterpret_cast<float2*>(outh + (size_t)r0 * OK + colb) =
                    make_float2(corr[0], corr[1]);
                *reinterpret_cast<float2*>(outh + (size_t)(r0 + 8) * OK + colb) =
                    make_float2(corr[2], corr[3]);
            }
        }
    }
}

// ---------------------------------------------------------------------------
extern "C" void kernel_launch(void* const* d_in, const int* in_sizes, int n_in,
                              void* d_out, int out_size) {
    const float* x           = (const float*)d_in[0];
    const float* W           = (const float*)d_in[1];
    const float* b           = (const float*)d_in[2];
    const float* A_sh        = (const float*)d_in[3];
    const float* B_sh        = (const float*)d_in[4];
    const float* A_tasks     = (const float*)d_in[5];
    const float* B_tasks     = (const float*)d_in[6];
    const float* task_scales = (const float*)d_in[7];
    float* out = (float*)d_out;
    (void)in_sizes; (void)n_in; (void)out_size;

    cudaFuncSetAttribute(fused_main, cudaFuncAttributeMaxDynamicSharedMemorySize,
                         SMEM_DYN);

    prep_wk<<<OK * DK / 2048, 256>>>(W);
    lora_y_kernel<<<MTOT / BM, 256>>>(x, A_sh, A_tasks);
    fused_main<<<dim3(OK / BN, MTOT / BM), 256, SMEM_DYN>>>(
        b, B_sh, B_tasks, task_scales, out);
}

// round 6
// speedup vs baseline: 1.1464x; 1.0464x over previous
#include <cuda_runtime.h>
#include <cuda_bf16.h>
#include <cstdint>

// ===========================================================================
// MTLoRALinear on sm_103a — legacy-tensor-pipe, BN=256 fat warp tiles.
//   prep_wk : W fp32 -> bf16 hi/lo
//   lora_y  : Y[M,80] = x @ concat(A_sh,A_tasks)^T (tf32) AND x -> bf16 hi/lo
//   fused   : P = x@W^T via 3-term bf16 m16n8k16 (hh+hl+lh), BM=128 BN=256
//             BK=32, 4-stage cp.async + ldmatrix, warp tile 64x64;
//             epilogue: 5 rank-16 tf32 corrections + streamed stores.
// ===========================================================================

namespace {
constexpr int MTOT = 32768, DK = 1024, OK = 1024;
constexpr int BM = 128, BN = 256, BK = 32;
constexpr int NCHUNK = DK / BK;           // 32
constexpr int NSTAGE = 4;
// stage layout: xhi(8K) xlo(8K) whi(16K) wlo(16K) = 48KB
constexpr int OFF_XHI = 0, OFF_XLO = 8192, OFF_WHI = 16384, OFF_WLO = 32768;
constexpr int STAGE_B = 49152;
constexpr int SMEM_DYN = NSTAGE * STAGE_B + 1024;   // 197632
constexpr int XST = 36;                   // lora_y smem stride
constexpr int EST = 84;                   // epilogue stride (conflict-free)
constexpr int EPI_B_OFF = 43520;          // Ys: 128*84*4=43008, Bs after
}

__device__ __align__(256) __nv_bfloat16 g_xhi[MTOT * DK];
__device__ __align__(256) __nv_bfloat16 g_xlo[MTOT * DK];
__device__ __align__(256) __nv_bfloat16 g_whi[OK * DK];
__device__ __align__(256) __nv_bfloat16 g_wlo[OK * DK];
__device__ __align__(256) float         g_Y[MTOT * 80];

// --------------------------- helpers ---------------------------------------
__device__ __forceinline__ uint32_t smem_u32(const void* p) {
    uint32_t a;
    asm("{ .reg .u64 t; cvta.to.shared.u64 t, %1; cvt.u32.u64 %0, t; }"
        : "=r"(a) : "l"(p));
    return a;
}
__device__ __forceinline__ void cp16(uint32_t dst, const void* src) {
    asm volatile("cp.async.cg.shared.global [%0], [%1], 16;"
                 :: "r"(dst), "l"(src) : "memory");
}
__device__ __forceinline__ void cp_commit() {
    asm volatile("cp.async.commit_group;" ::: "memory");
}
template <int N> __device__ __forceinline__ void cp_wait() {
    asm volatile("cp.async.wait_group %0;" :: "n"(N) : "memory");
}
__device__ __forceinline__ void ldsm4(uint32_t& r0, uint32_t& r1, uint32_t& r2,
                                      uint32_t& r3, uint32_t a) {
    asm volatile("ldmatrix.sync.aligned.m8n8.x4.shared.b16 {%0,%1,%2,%3}, [%4];"
                 : "=r"(r0), "=r"(r1), "=r"(r2), "=r"(r3) : "r"(a));
}
__device__ __forceinline__ void ldsm2(uint32_t& r0, uint32_t& r1, uint32_t a) {
    asm volatile("ldmatrix.sync.aligned.m8n8.x2.shared.b16 {%0,%1}, [%2];"
                 : "=r"(r0), "=r"(r1) : "r"(a));
}
__device__ __forceinline__ void mma_bf16(float* c, const uint32_t* a,
                                         const uint32_t* b) {
    asm volatile(
        "mma.sync.aligned.m16n8k16.row.col.f32.bf16.bf16.f32 "
        "{%0,%1,%2,%3}, {%4,%5,%6,%7}, {%8,%9}, {%0,%1,%2,%3};"
        : "+f"(c[0]), "+f"(c[1]), "+f"(c[2]), "+f"(c[3])
        : "r"(a[0]), "r"(a[1]), "r"(a[2]), "r"(a[3]), "r"(b[0]), "r"(b[1]));
}
__device__ __forceinline__ uint32_t tf32_rna(float x) {
    uint32_t u;
    asm("cvt.rna.tf32.f32 %0, %1;" : "=r"(u) : "f"(x));
    return u;
}
__device__ __forceinline__ float tf32f(float x) {
    return __uint_as_float(tf32_rna(x));
}
__device__ __forceinline__ void mma_tf32(float* c, const uint32_t* a,
                                         const uint32_t* b) {
    asm volatile(
        "mma.sync.aligned.m16n8k8.row.col.f32.tf32.tf32.f32 "
        "{%0,%1,%2,%3}, {%4,%5,%6,%7}, {%8,%9}, {%0,%1,%2,%3};"
        : "+f"(c[0]), "+f"(c[1]), "+f"(c[2]), "+f"(c[3])
        : "r"(a[0]), "r"(a[1]), "r"(a[2]), "r"(a[3]), "r"(b[0]), "r"(b[1]));
}
__device__ __forceinline__ void mma_tf32_dc(float* d, const float* c,
                                            const uint32_t* a, const uint32_t* b) {
    asm volatile(
        "mma.sync.aligned.m16n8k8.row.col.f32.tf32.tf32.f32 "
        "{%0,%1,%2,%3}, {%4,%5,%6,%7}, {%8,%9}, {%10,%11,%12,%13};"
        : "=f"(d[0]), "=f"(d[1]), "=f"(d[2]), "=f"(d[3])
        : "r"(a[0]), "r"(a[1]), "r"(a[2]), "r"(a[3]), "r"(b[0]), "r"(b[1]),
          "f"(c[0]), "f"(c[1]), "f"(c[2]), "f"(c[3]));
}
__device__ __forceinline__ void split8(const float4& a, const float4& b,
                                       uint4& h, uint4& l) {
    float f[8] = {a.x, a.y, a.z, a.w, b.x, b.y, b.z, b.w};
    uint32_t hp[4], lp[4];
#pragma unroll
    for (int i = 0; i < 4; i++) {
        __nv_bfloat16 h0 = __float2bfloat16_rn(f[2 * i]);
        __nv_bfloat16 h1 = __float2bfloat16_rn(f[2 * i + 1]);
        __nv_bfloat16 l0 = __float2bfloat16_rn(f[2 * i] - __bfloat162float(h0));
        __nv_bfloat16 l1 = __float2bfloat16_rn(f[2 * i + 1] - __bfloat162float(h1));
        hp[i] = (uint32_t)__bfloat16_as_ushort(h0) |
                ((uint32_t)__bfloat16_as_ushort(h1) << 16);
        lp[i] = (uint32_t)__bfloat16_as_ushort(l0) |
                ((uint32_t)__bfloat16_as_ushort(l1) << 16);
    }
    h = make_uint4(hp[0], hp[1], hp[2], hp[3]);
    l = make_uint4(lp[0], lp[1], lp[2], lp[3]);
}
__device__ __forceinline__ void split4(const float4& v, uint2& h, uint2& l) {
    __nv_bfloat16 h0 = __float2bfloat16_rn(v.x), h1 = __float2bfloat16_rn(v.y);
    __nv_bfloat16 h2 = __float2bfloat16_rn(v.z), h3 = __float2bfloat16_rn(v.w);
    __nv_bfloat16 l0 = __float2bfloat16_rn(v.x - __bfloat162float(h0));
    __nv_bfloat16 l1 = __float2bfloat16_rn(v.y - __bfloat162float(h1));
    __nv_bfloat16 l2 = __float2bfloat16_rn(v.z - __bfloat162float(h2));
    __nv_bfloat16 l3 = __float2bfloat16_rn(v.w - __bfloat162float(h3));
    h.x = (uint32_t)__bfloat16_as_ushort(h0) | ((uint32_t)__bfloat16_as_ushort(h1) << 16);
    h.y = (uint32_t)__bfloat16_as_ushort(h2) | ((uint32_t)__bfloat16_as_ushort(h3) << 16);
    l.x = (uint32_t)__bfloat16_as_ushort(l0) | ((uint32_t)__bfloat16_as_ushort(l1) << 16);
    l.y = (uint32_t)__bfloat16_as_ushort(l2) | ((uint32_t)__bfloat16_as_ushort(l3) << 16);
}
// 128-row x 32-col bf16 tile: 64B rows, 4x16B chunks, XOR swizzle (R3-proven)
__device__ __forceinline__ uint32_t tswz32(int row, int ch) {
    return (uint32_t)(row * 64 + ((ch ^ ((row >> 1) & 3)) << 4));
}

// --------------------------- prep W ----------------------------------------
__global__ __launch_bounds__(256) void prep_wk(const float* __restrict__ W) {
    size_t i = ((size_t)blockIdx.x * 256 + threadIdx.x) * 8;
    float4 a = *reinterpret_cast<const float4*>(W + i);
    float4 b = *reinterpret_cast<const float4*>(W + i + 4);
    uint4 h, l;
    split8(a, b, h, l);
    *reinterpret_cast<uint4*>(g_whi + i) = h;
    *reinterpret_cast<uint4*>(g_wlo + i) = l;
}

// ---------------- lora_y + inline x -> bf16 hi/lo split --------------------
__global__ __launch_bounds__(256) void lora_y_kernel(
    const float* __restrict__ x,
    const float* __restrict__ A_sh,
    const float* __restrict__ A_tasks)
{
    __shared__ float Xs[BM * XST];
    __shared__ float Ws[BM * XST];

    const int tid = threadIdx.x;
    const int lane = tid & 31, wid = tid >> 5;
    const int wm = wid >> 2, wn = wid & 3;
    const int m0 = blockIdx.x * BM;
    const int lr = tid >> 3;
    const int lc = (tid & 7) << 2;

    const float* xg = x + (size_t)(m0 + lr) * DK + lc;
    const float* ag[4];
    bool av[4];
#pragma unroll
    for (int i = 0; i < 4; i++) {
        const int r = lr + 32 * i;
        if (r < 16)      { ag[i] = A_sh + (size_t)r * DK + lc; av[i] = true; }
        else if (r < 80) { ag[i] = A_tasks + (size_t)(r - 16) * DK + lc; av[i] = true; }
        else             { ag[i] = A_sh + lc; av[i] = false; }
    }

    float4 px[4], pw[4];
    const float4 z4 = make_float4(0.f, 0.f, 0.f, 0.f);
#pragma unroll
    for (int i = 0; i < 4; i++) {
        px[i] = *reinterpret_cast<const float4*>(xg + (size_t)(32 * i) * DK);
        pw[i] = av[i] ? *reinterpret_cast<const float4*>(ag[i]) : z4;
    }

    float c[4][4][4];
#pragma unroll
    for (int i = 0; i < 4; i++)
#pragma unroll
        for (int j = 0; j < 4; j++)
#pragma unroll
            for (int q = 0; q < 4; q++) c[i][j][q] = 0.f;

    for (int kc = 0; kc < DK; kc += 32) {
        __syncthreads();
#pragma unroll
        for (int i = 0; i < 4; i++) {
            {
                uint2 h, l;
                split4(px[i], h, l);
                const size_t go = (size_t)(m0 + lr + 32 * i) * DK + kc + lc;
                *reinterpret_cast<uint2*>(g_xhi + go) = h;
                *reinterpret_cast<uint2*>(g_xlo + go) = l;
            }
            float* xs = &Xs[(lr + 32 * i) * XST + lc];
            xs[0] = tf32f(px[i].x); xs[1] = tf32f(px[i].y);
            xs[2] = tf32f(px[i].z); xs[3] = tf32f(px[i].w);
            float* ws = &Ws[(lr + 32 * i) * XST + lc];
            ws[0] = tf32f(pw[i].x); ws[1] = tf32f(pw[i].y);
            ws[2] = tf32f(pw[i].z); ws[3] = tf32f(pw[i].w);
        }
        __syncthreads();
        if (kc + 32 < DK) {
#pragma unroll
            for (int i = 0; i < 4; i++) {
                px[i] = *reinterpret_cast<const float4*>(xg + (size_t)(32 * i) * DK + kc + 32);
                pw[i] = av[i] ? *reinterpret_cast<const float4*>(ag[i] + kc + 32) : z4;
            }
        }
#pragma unroll
        for (int ks = 0; ks < 4; ks++) {
            const int ak = ks * 8 + (lane & 3);
            const int ar = wm * 64 + (lane >> 2);
            uint32_t a[4][4];
#pragma unroll
            for (int i = 0; i < 4; i++) {
                const float* base = &Xs[(ar + i * 16) * XST + ak];
                a[i][0] = __float_as_uint(base[0]);
                a[i][1] = __float_as_uint(base[8 * XST]);
                a[i][2] = __float_as_uint(base[4]);
                a[i][3] = __float_as_uint(base[8 * XST + 4]);
            }
            uint32_t b[4][2];
            const int bn = wn * 32 + (lane >> 2);
#pragma unroll
            for (int j = 0; j < 4; j++) {
                const float* base = &Ws[(bn + j * 8) * XST + ak];
                b[j][0] = __float_as_uint(base[0]);
                b[j][1] = __float_as_uint(base[4]);
            }
#pragma unroll
            for (int i = 0; i < 4; i++)
#pragma unroll
                for (int j = 0; j < 4; j++)
                    mma_tf32(c[i][j], a[i], b[j]);
        }
    }

#pragma unroll
    for (int j = 0; j < 4; j++) {
        const int colb = wn * 32 + j * 8 + (lane & 3) * 2;
        if (colb < 80) {
#pragma unroll
            for (int i = 0; i < 4; i++) {
                const int r0 = m0 + wm * 64 + i * 16 + (lane >> 2);
                *reinterpret_cast<float2*>(g_Y + (size_t)r0 * 80 + colb) =
                    make_float2(c[i][j][0], c[i][j][1]);
                *reinterpret_cast<float2*>(g_Y + (size_t)(r0 + 8) * 80 + colb) =
                    make_float2(c[i][j][2], c[i][j][3]);
            }
        }
    }
}

// --------------------------- fused main ------------------------------------
__global__ __launch_bounds__(256, 1) void fused_main(
    const float* __restrict__ bias,
    const float* __restrict__ B_sh,
    const float* __restrict__ B_tasks,
    const float* __restrict__ task_scales,
    float* __restrict__ out)
{
    extern __shared__ char dsm[];
    const uint32_t raw = smem_u32(dsm);
    const uint32_t base = (raw + 1023u) & ~1023u;
    char* sm = dsm + (base - raw);

    const int tid = threadIdx.x, wid = tid >> 5, lane = tid & 31;
    const int wm = wid >> 2, wn = wid & 3;      // 2 x 4 warps, warp tile 64x64
    const int m0 = blockIdx.y * BM, n0 = blockIdx.x * BN;

    // ---- cp.async mapping: thread -> row (tid>>2), 16B chunk (tid&3) ------
    const int trow = tid >> 2, tch = tid & 3;   // trow 0..63
    const uint32_t dsw = tswz32(trow, tch);     // swz(row+64p) = swz(row)+p*4096
    const __nv_bfloat16* xh = g_xhi + (size_t)(m0 + trow) * DK + tch * 8;
    const __nv_bfloat16* xl = g_xlo + (size_t)(m0 + trow) * DK + tch * 8;
    const __nv_bfloat16* wh = g_whi + (size_t)(n0 + trow) * DK + tch * 8;
    const __nv_bfloat16* wl = g_wlo + (size_t)(n0 + trow) * DK + tch * 8;

    auto issue = [&](int chunk) {
        const uint32_t sb = base + (chunk & (NSTAGE - 1)) * STAGE_B;
        const int ko = chunk * BK;
#pragma unroll
        for (int p = 0; p < 2; p++) {
            cp16(sb + OFF_XHI + p * 4096 + dsw, xh + (size_t)p * 64 * DK + ko);
            cp16(sb + OFF_XLO + p * 4096 + dsw, xl + (size_t)p * 64 * DK + ko);
        }
#pragma unroll
        for (int p = 0; p < 4; p++) {
            cp16(sb + OFF_WHI + p * 4096 + dsw, wh + (size_t)p * 64 * DK + ko);
            cp16(sb + OFF_WLO + p * 4096 + dsw, wl + (size_t)p * 64 * DK + ko);
        }
        cp_commit();
    };

    issue(0); issue(1); issue(2);

    float c[8][4][4];
#pragma unroll
    for (int j = 0; j < 8; j++)
#pragma unroll
        for (int i = 0; i < 4; i++)
#pragma unroll
            for (int q = 0; q < 4; q++) c[j][i][q] = 0.f;

    // ldmatrix per-lane address components
    const int qrow = lane & 7, q = lane >> 3;
    const int a_row_off = wm * 64 + (q & 1) * 8 + qrow;  // + i*16
    const int a_ch_off = q >> 1;                         // + ks*2
    const int b_row_off = wn * 64 + (lane & 7);          // + j*8
    const int b_ch_off = (lane >> 3) & 1;                // + ks*2

    for (int it = 0; it < NCHUNK; it++) {
        cp_wait<2>();
        __syncthreads();
        const uint32_t sb = base + (it & (NSTAGE - 1)) * STAGE_B;
#pragma unroll
        for (int ks = 0; ks < 2; ks++) {
            uint32_t ahi[4][4], alo[4][4];
#pragma unroll
            for (int i = 0; i < 4; i++) {
                const int row = a_row_off + i * 16;
                const uint32_t o = tswz32(row, ks * 2 + a_ch_off);
                ldsm4(ahi[i][0], ahi[i][1], ahi[i][2], ahi[i][3],
                      sb + OFF_XHI + o);
                ldsm4(alo[i][0], alo[i][1], alo[i][2], alo[i][3],
                      sb + OFF_XLO + o);
            }
#pragma unroll
            for (int j = 0; j < 8; j++) {
                const int row = b_row_off + j * 8;
                const uint32_t o = tswz32(row, ks * 2 + b_ch_off);
                uint32_t bhi[2], blo[2];
                ldsm2(bhi[0], bhi[1], sb + OFF_WHI + o);
                ldsm2(blo[0], blo[1], sb + OFF_WLO + o);
#pragma unroll
                for (int i = 0; i < 4; i++) mma_bf16(c[j][i], ahi[i], bhi);
#pragma unroll
                for (int i = 0; i < 4; i++) mma_bf16(c[j][i], ahi[i], blo);
#pragma unroll
                for (int i = 0; i < 4; i++) mma_bf16(c[j][i], alo[i], bhi);
            }
        }
        if (it + 3 < NCHUNK) issue(it + 3);
        else cp_commit();
    }
    cp_wait<0>();
    __syncthreads();

    // ---- bias ------------------------------------------------------------
#pragma unroll
    for (int j = 0; j < 8; j++) {
        const int col = n0 + wn * 64 + j * 8 + (lane & 3) * 2;
        const float b0 = __ldg(bias + col);
        const float b1 = __ldg(bias + col + 1);
#pragma unroll
        for (int i = 0; i < 4; i++) {
            c[j][i][0] += b0; c[j][i][1] += b1;
            c[j][i][2] += b0; c[j][i][3] += b1;
        }
    }

    // ---- epilogue: stage Y[128x80] and scaled B_all[256x80] once ----------
    float* Ys = reinterpret_cast<float*>(sm);
    float* Bs = reinterpret_cast<float*>(sm + EPI_B_OFF);
    {
        const int srow = tid >> 1, half = tid & 1;
        const float* ys = g_Y + (size_t)(m0 + srow) * 80 + half * 40;
        float* yd = Ys + srow * EST + half * 40;
#pragma unroll
        for (int g = 0; g < 10; g++) {
            float4 v = __ldg(reinterpret_cast<const float4*>(ys + g * 4));
            yd[g * 4 + 0] = tf32f(v.x); yd[g * 4 + 1] = tf32f(v.y);
            yd[g * 4 + 2] = tf32f(v.z); yd[g * 4 + 3] = tf32f(v.w);
        }
        float sc[4];
#pragma unroll
        for (int t = 0; t < 4; t++) sc[t] = __ldg(task_scales + t);
        // one thread per B row (256 rows)
        float* bd = Bs + tid * EST;
#pragma unroll
        for (int g = 0; g < 20; g++) {
            const int k0 = g * 4;
            const float* src;
            float s;
            if (k0 < 16) { src = B_sh + (size_t)(n0 + tid) * 16 + k0; s = 1.f; }
            else {
                const int t = (k0 - 16) >> 4, rr = (k0 - 16) & 15;
                src = B_tasks + ((size_t)t * OK + n0 + tid) * 16 + rr;
                s = sc[t];
            }
            float4 v = __ldg(reinterpret_cast<const float4*>(src));
            bd[g * 4 + 0] = tf32f(v.x * s); bd[g * 4 + 1] = tf32f(v.y * s);
            bd[g * 4 + 2] = tf32f(v.z * s); bd[g * 4 + 3] = tf32f(v.w * s);
        }
    }
    __syncthreads();

    const int ar = wm * 64 + (lane >> 2);
    const int kk = lane & 3;
    for (int h = 0; h < 5; h++) {
        uint32_t ya[4][2][4];
#pragma unroll
        for (int i = 0; i < 4; i++)
#pragma unroll
            for (int ks = 0; ks < 2; ks++) {
                const float* bp = &Ys[(ar + i * 16) * EST + h * 16 + ks * 8 + kk];
                ya[i][ks][0] = __float_as_uint(bp[0]);
                ya[i][ks][1] = __float_as_uint(bp[8 * EST]);
                ya[i][ks][2] = __float_as_uint(bp[4]);
                ya[i][ks][3] = __float_as_uint(bp[8 * EST + 4]);
            }
        float* outh = out + (size_t)h * MTOT * OK;
#pragma unroll
        for (int j = 0; j < 8; j++) {
            uint32_t yb[2][2];
            const int bn = wn * 64 + j * 8 + (lane >> 2);
#pragma unroll
            for (int ks = 0; ks < 2; ks++) {
                const float* bp = &Bs[bn * EST + h * 16 + ks * 8 + kk];
                yb[ks][0] = __float_as_uint(bp[0]);
                yb[ks][1] = __float_as_uint(bp[4]);
            }
            const int colb = n0 + wn * 64 + j * 8 + (lane & 3) * 2;
#pragma unroll
            for (int i = 0; i < 4; i++) {
                float corr[4];
                mma_tf32_dc(corr, c[j][i], ya[i][0], yb[0]);
                mma_tf32(corr, ya[i][1], yb[1]);
                const int r0 = m0 + wm * 64 + i * 16 + (lane >> 2);
                *reinterpret_cast<float2*>(outh + (size_t)r0 * OK + colb) =
                    make_float2(corr[0], corr[1]);
                *reinterpret_cast<float2*>(outh + (size_t)(r0 + 8) * OK + colb) =
                    make_float2(corr[2], corr[3]);
            }
        }
    }
}

// ---------------------------------------------------------------------------
extern "C" void kernel_launch(void* const* d_in, const int* in_sizes, int n_in,
                              void* d_out, int out_size) {
    const float* x           = (const float*)d_in[0];
    const float* W           = (const float*)d_in[1];
    const float* b           = (const float*)d_in[2];
    const float* A_sh        = (const float*)d_in[3];
    const float* B_sh        = (const float*)d_in[4];
    const float* A_tasks     = (const float*)d_in[5];
    const float* B_tasks     = (const float*)d_in[6];
    const float* task_scales = (const float*)d_in[7];
    float* out = (float*)d_out;
    (void)in_sizes; (void)n_in; (void)out_size;

    cudaFuncSetAttribute(fused_main, cudaFuncAttributeMaxDynamicSharedMemorySize,
                         SMEM_DYN);

    prep_wk<<<OK * DK / 2048, 256>>>(W);
    lora_y_kernel<<<MTOT / BM, 256>>>(x, A_sh, A_tasks);
    fused_main<<<dim3(OK / BN, MTOT / BM), 256, SMEM_DYN>>>(
        b, B_sh, B_tasks, task_scales, out);
}